// round 15
// baseline (speedup 1.0000x reference)
#include <cuda_runtime.h>
#include <cuda_bf16.h>
#include <cuda_fp16.h>
#include <cstdint>
#include <math.h>

#define B 4
#define C 64
#define N 4096

// ---------------------------------------------------------------------------
// Scratch (device globals, allocation-free rule)
// ---------------------------------------------------------------------------
__device__ __align__(16) __nv_bfloat16 g_Qb[B * N * 8];   // [b][n][8], scaled 0.125*log2e
__device__ __align__(16) __nv_bfloat16 g_Kb[B * N * 8];   // [b][m][8]
__device__ __align__(16) __half        g_Vt[B * C * N];   // [b][ch][m] transposed, fp16
__device__ float g_gate[B * C];
__device__ float g_part[B * 64 * C];                       // per-CTA channel sums

// ---------------------------------------------------------------------------
// Helpers
// ---------------------------------------------------------------------------
__device__ __forceinline__ uint32_t smem_u32(const void* p) {
    uint32_t a;
    asm("{ .reg .u64 t; cvta.to.shared.u64 t, %1; cvt.u32.u64 %0, t; }" : "=r"(a) : "l"(p));
    return a;
}
__device__ __forceinline__ uint32_t swz128(uint32_t o) {
    return o ^ ((o >> 3) & 0x70);
}
#define CVT2(r, a, b) \
    asm("cvt.rn.satfinite.bf16x2.f32 %0, %1, %2;" : "=r"(r) : "f"(b), "f"(a))
#define PACKH2(r, lo, hi) \
    asm("cvt.rn.f16x2.f32 %0, %1, %2;" : "=r"(r) : "f"(hi), "f"(lo))
#define EX2H2(r, s) \
    asm("ex2.approx.f16x2 %0, %1;" : "=r"(r) : "r"(s))
#define ONESH2 0x3C003C00u

#define CP_ASYNC16(dst, src) \
    asm volatile("cp.async.cg.shared.global [%0], [%1], 16;" :: "r"(dst), "l"(src) : "memory")
#define CP_COMMIT() asm volatile("cp.async.commit_group;" ::: "memory")
#define CP_WAIT0()  asm volatile("cp.async.wait_group 0;" ::: "memory")

#define LDSM_X2(r0, r1, a) \
    asm volatile("ldmatrix.sync.aligned.m8n8.x2.shared.b16 {%0,%1}, [%2];" \
                 : "=r"(r0), "=r"(r1) : "r"(a))
#define LDSM_X4(r0, r1, r2, r3, a) \
    asm volatile("ldmatrix.sync.aligned.m8n8.x4.shared.b16 {%0,%1,%2,%3}, [%4];" \
                 : "=r"(r0), "=r"(r1), "=r"(r2), "=r"(r3) : "r"(a))

__device__ __forceinline__ void mma_k8(float& c0, float& c1, float& c2, float& c3,
                                       uint32_t a0, uint32_t a1, uint32_t b0) {
    asm volatile(
        "mma.sync.aligned.m16n8k8.row.col.f32.bf16.bf16.f32 "
        "{%0,%1,%2,%3}, {%4,%5}, {%6}, {%0,%1,%2,%3};"
        : "+f"(c0), "+f"(c1), "+f"(c2), "+f"(c3)
        : "r"(a0), "r"(a1), "r"(b0));
}
__device__ __forceinline__ void mma_k16(float* c, const uint32_t* a,
                                        uint32_t b0, uint32_t b1) {
    asm volatile(
        "mma.sync.aligned.m16n8k16.row.col.f32.bf16.bf16.f32 "
        "{%0,%1,%2,%3}, {%4,%5,%6,%7}, {%8,%9}, {%0,%1,%2,%3};"
        : "+f"(c[0]), "+f"(c[1]), "+f"(c[2]), "+f"(c[3])
        : "r"(a[0]), "r"(a[1]), "r"(a[2]), "r"(a[3]), "r"(b0), "r"(b1));
}
__device__ __forceinline__ void mma_k16h(float* c, const uint32_t* a,
                                         uint32_t b0, uint32_t b1) {
    asm volatile(
        "mma.sync.aligned.m16n8k16.row.col.f32.f16.f16.f32 "
        "{%0,%1,%2,%3}, {%4,%5,%6,%7}, {%8,%9}, {%0,%1,%2,%3};"
        : "+f"(c[0]), "+f"(c[1]), "+f"(c[2]), "+f"(c[3])
        : "r"(a[0]), "r"(a[1]), "r"(a[2]), "r"(a[3]), "r"(b0), "r"(b1));
}

#define QSCALE (0.125f * 1.4426950408889634f)

// ---------------------------------------------------------------------------
// Kernel 1: QKV via HMMA + fused SE partial sums (R14 proven: 6.8 us).
// 256 CTAs x 256 thr, 64 px/CTA, static smem.
// ---------------------------------------------------------------------------
#define XP 68
#define QOFF_W     0
#define QOFF_BIAS  10240
#define QOFF_XB    10880
#define QOFF_UNION 19072
#define QSMEM      (19072 + 64 * XP * 4)    // 36480

__global__ void __launch_bounds__(256) qkv_kernel(
    const float* __restrict__ x,
    const float* __restrict__ Wq, const float* __restrict__ bq,
    const float* __restrict__ Wk, const float* __restrict__ bk,
    const float* __restrict__ Wv, const float* __restrict__ bv) {
    __shared__ __align__(128) char sm[QSMEM];
    uint32_t sb = smem_u32(sm);
    int t = threadIdx.x, lane = t & 31, w = t >> 5;
    int cta = blockIdx.x;
    int bb = cta >> 6;
    int n0 = (cta & 63) * 64;
    int pix0 = bb * N + n0;
    float* sXf = (float*)(sm + QOFF_UNION);          // [64][XP]
    float* sbias = (float*)(sm + QOFF_BIAS);

    for (int i = t; i < 1280; i += 256) {            // 80 rows x 16 float4
        int r = i >> 4, c4 = i & 15;
        const float* src = (r < 8) ? (Wq + r * 64)
                         : (r < 16) ? (Wk + (r - 8) * 64)
                                    : (Wv + (r - 16) * 64);
        float4 ww = ((const float4*)src)[c4];
        uint32_t p0, p1;
        CVT2(p0, ww.x, ww.y);
        CVT2(p1, ww.z, ww.w);
        uint32_t gr = swz128((uint32_t)(r * 128 + (c4 >> 1) * 16)) + (c4 & 1) * 8;
        *(uint32_t*)(sm + QOFF_W + gr) = p0;
        *(uint32_t*)(sm + QOFF_W + gr + 4) = p1;
    }
    if (t < 80) sbias[t] = (t < 8) ? bq[t] : (t < 16) ? bk[t - 8] : bv[t - 16];

    {
        const float4* xs = (const float4*)(x + (size_t)bb * C * N + n0);
#pragma unroll
        for (int j = 0; j < 4; j++) {
            int id = t + 256 * j;
            int row = id >> 4, c4 = id & 15;
            *(float4*)(sXf + row * XP + c4 * 4) = xs[(size_t)row * (N / 4) + c4];
        }
    }
    __syncthreads();

    if (t < 64) {
        float s = 0.0f;
#pragma unroll 8
        for (int px = 0; px < 64; px++) s += sXf[t * XP + px];
        g_part[((size_t)bb * 64 + (cta & 63)) * C + t] = s;
    }

    {
        int px = t & 63, seg = t >> 6;
#pragma unroll
        for (int s = 0; s < 2; s++) {
            int ch0 = seg * 16 + s * 8;
            uint32_t u[4];
#pragma unroll
            for (int kk = 0; kk < 4; kk++) {
                float f0 = sXf[(ch0 + 2 * kk) * XP + px];
                float f1 = sXf[(ch0 + 2 * kk + 1) * XP + px];
                CVT2(u[kk], f0, f1);
            }
            uint32_t off = swz128((uint32_t)(px * 128 + ch0 * 2));
            *(uint4*)(sm + QOFF_XB + off) = make_uint4(u[0], u[1], u[2], u[3]);
        }
    }
    __syncthreads();

    int wpx = (w >> 1) * 16, nhalf = w & 1;
    int grp0 = nhalf ? 3 : 0, ngrp = nhalf ? 2 : 3;
    float o6[6][4] = {};
    {
        uint32_t a_row = (uint32_t)((wpx + (lane & 15)) * 128 + (lane >> 4) * 16);
        uint32_t b_row = (uint32_t)((((lane >> 4) * 8) + (lane & 7)) * 128 + ((lane >> 3) & 1) * 16);
#pragma unroll
        for (int ks = 0; ks < 4; ks++) {
            uint32_t a[4];
            LDSM_X4(a[0], a[1], a[2], a[3], sb + QOFF_XB + swz128(a_row + ks * 32));
#pragma unroll
            for (int gi = 0; gi < 3; gi++) {
                if (gi >= ngrp) break;
                uint32_t b0, b1, b2, b3;
                LDSM_X4(b0, b1, b2, b3,
                        sb + QOFF_W + swz128(b_row + (uint32_t)((grp0 + gi) * 2048) + ks * 32));
                mma_k16(o6[2 * gi], a, b0, b1);
                mma_k16(o6[2 * gi + 1], a, b2, b3);
            }
        }
    }

    int g = lane >> 2, t4 = lane & 3;
    if (nhalf == 0) {
        {
            float bA = sbias[2 * t4], bB = sbias[2 * t4 + 1];
            uint32_t r0, r1;
            CVT2(r0, (o6[0][0] + bA) * QSCALE, (o6[0][1] + bB) * QSCALE);
            CVT2(r1, (o6[0][2] + bA) * QSCALE, (o6[0][3] + bB) * QSCALE);
            *(uint32_t*)(g_Qb + (size_t)(pix0 + wpx + g) * 8 + 2 * t4) = r0;
            *(uint32_t*)(g_Qb + (size_t)(pix0 + wpx + 8 + g) * 8 + 2 * t4) = r1;
        }
        {
            float bA = sbias[8 + 2 * t4], bB = sbias[8 + 2 * t4 + 1];
            uint32_t r0, r1;
            CVT2(r0, o6[1][0] + bA, o6[1][1] + bB);
            CVT2(r1, o6[1][2] + bA, o6[1][3] + bB);
            *(uint32_t*)(g_Kb + (size_t)(pix0 + wpx + g) * 8 + 2 * t4) = r0;
            *(uint32_t*)(g_Kb + (size_t)(pix0 + wpx + 8 + g) * 8 + 2 * t4) = r1;
        }
    }
    __syncthreads();
    {
        __half* sV = (__half*)(sm + QOFF_UNION);
        int ntv0 = nhalf ? 0 : 2;
        int chbase = nhalf ? 32 : 0;
#pragma unroll
        for (int k = 0; k < 4; k++) {
            int ch = chbase + k * 8 + 2 * t4;
            float b0f = sbias[16 + ch], b1f = sbias[16 + ch + 1];
            float* oo = o6[ntv0 + k];
            sV[ch * 72 + wpx + g]           = __float2half(oo[0] + b0f);
            sV[(ch + 1) * 72 + wpx + g]     = __float2half(oo[1] + b1f);
            sV[ch * 72 + wpx + 8 + g]       = __float2half(oo[2] + b0f);
            sV[(ch + 1) * 72 + wpx + 8 + g] = __float2half(oo[3] + b1f);
        }
    }
    __syncthreads();
    {
        int r = t >> 2, off = (t & 3) * 32;
        uint4 v0 = *(const uint4*)(sm + QOFF_UNION + r * 144 + off);
        uint4 v1 = *(const uint4*)(sm + QOFF_UNION + r * 144 + off + 16);
        char* dst = (char*)(g_Vt + (size_t)(bb * C + r) * N + n0) + off;
        *(uint4*)dst = v0;
        *(uint4*)(dst + 16) = v1;
    }
}

// ---------------------------------------------------------------------------
// Kernel 2: SE gate MLP. 4 blocks x 64 thr; sums the 64 per-CTA partials.
// ---------------------------------------------------------------------------
__global__ void gate_mlp_kernel(const float* __restrict__ W1, const float* __restrict__ b1,
                                const float* __restrict__ W2, const float* __restrict__ b2) {
    __shared__ float savg[C];
    __shared__ float shid[4];
    int b = blockIdx.x, t = threadIdx.x;   // 64 threads
    float s = 0.0f;
#pragma unroll 8
    for (int j = 0; j < 64; j++) s += g_part[((size_t)b * 64 + j) * C + t];
    savg[t] = s * (1.0f / (float)N);
    __syncthreads();
    if (t < 4) {
        float h = b1[t];
#pragma unroll
        for (int c = 0; c < C; c++) h = fmaf(W1[t * C + c], savg[c], h);
        shid[t] = fmaxf(h, 0.0f);
    }
    __syncthreads();
    float gg = b2[t];
#pragma unroll
    for (int j = 0; j < 4; j++) gg = fmaf(W2[t * 4 + j], shid[j], gg);
    g_gate[b * C + t] = 1.0f / (1.0f + __expf(-gg));
}

// ---------------------------------------------------------------------------
// Kernel 3: HMMA flash attention (R12 proven: ~38 us).
// ---------------------------------------------------------------------------
#define OFF_GATE 0
#define OFF_K    256
#define OFF_V    (256 + 8192)
#define SMEM_ATTN (256 + 8192 + 4 * 17408)
#define VPITCH 272
#define REDP 66

__global__ void __launch_bounds__(128, 2) attn_kernel(float* __restrict__ out) {
    extern __shared__ char dsm[];
    uint32_t sb = smem_u32(dsm);
    int tid = threadIdx.x, w = tid >> 5, lane = tid & 31;
    int g = lane >> 2, t4 = lane & 3;
    int qg = w & 1, kh = w >> 1;
    int bb = blockIdx.x >> 6, qb = blockIdx.x & 63;
    int q0 = qb * 64 + qg * 32;

    if (tid < C) ((float*)(dsm + OFF_GATE))[tid] = g_gate[bb * C + tid];

    uint32_t qa[4];
    {
        const __nv_bfloat16* Qp = g_Qb + ((size_t)bb * N + q0) * 8 + t4 * 2;
#pragma unroll
        for (int r = 0; r < 4; r++)
            qa[r] = *(const uint32_t*)(Qp + (size_t)(r * 8 + g) * 8);
    }

    const char* kgb = (const char*)(g_Kb + (size_t)bb * N * 8);
    const char* vgb = (const char*)(g_Vt + (size_t)bb * C * N);

    uint32_t kfb = sb + OFF_K + kh * 4096 + (lane & 15) * 16;
    int vg2 = lane >> 3, vr = lane & 7;
    uint32_t vfb = sb + OFF_V + kh * 34816
                 + (uint32_t)(((vg2 >> 1) * 8 + vr) * VPITCH + (vg2 & 1) * 16);

#pragma unroll
    for (int h = 0; h < 2; h++) {
        int key0 = h * 2048;
        CP_ASYNC16(sb + OFF_K + h * 4096 + tid * 16, kgb + (size_t)key0 * 16 + tid * 16);
#pragma unroll
        for (int j = 0; j < 8; j++) {
            int id = tid + 128 * j, row = id >> 4, c16 = id & 15;
            CP_ASYNC16(sb + OFF_V + h * 34816 + row * VPITCH + c16 * 16,
                       vgb + ((size_t)row * N + key0) * 2 + c16 * 16);
        }
    }
    CP_COMMIT();

    float o[2][8][4] = {};
    float sacc[2][4] = {};

#pragma unroll 1
    for (int kt = 0; kt < 16; kt++) {
        int buf = kt & 1;
        CP_WAIT0();
        __syncthreads();
        if (kt + 1 < 16) {
            int nb = (kt + 1) & 1;
#pragma unroll
            for (int h = 0; h < 2; h++) {
                int key0 = h * 2048 + (kt + 1) * 128;
                CP_ASYNC16(sb + OFF_K + (h * 2 + nb) * 2048 + tid * 16,
                           kgb + (size_t)key0 * 16 + tid * 16);
#pragma unroll
                for (int j = 0; j < 8; j++) {
                    int id = tid + 128 * j, row = id >> 4, c16 = id & 15;
                    CP_ASYNC16(sb + OFF_V + (h * 2 + nb) * 17408 + row * VPITCH + c16 * 16,
                               vgb + ((size_t)row * N + key0) * 2 + c16 * 16);
                }
            }
            CP_COMMIT();
        }
        uint32_t ka = kfb + buf * 2048;
        uint32_t va = vfb + buf * 17408;
#pragma unroll
        for (int nt2 = 0; nt2 < 8; nt2++) {
            uint32_t kk0, kk1;
            LDSM_X2(kk0, kk1, ka + nt2 * 256);
            uint32_t a[2][4];
#pragma unroll
            for (int blk = 0; blk < 2; blk++) {
                float c0 = 0, c1 = 0, c2 = 0, c3 = 0, c4 = 0, c5 = 0, c6 = 0, c7 = 0;
                mma_k8(c0, c1, c2, c3, qa[2 * blk], qa[2 * blk + 1], kk0);
                mma_k8(c4, c5, c6, c7, qa[2 * blk], qa[2 * blk + 1], kk1);
                uint32_t s01, s23, s45, s67;
                PACKH2(s01, c0, c1);
                PACKH2(s23, c2, c3);
                PACKH2(s45, c4, c5);
                PACKH2(s67, c6, c7);
                EX2H2(a[blk][0], s01);
                EX2H2(a[blk][1], s23);
                EX2H2(a[blk][2], s45);
                EX2H2(a[blk][3], s67);
                mma_k16h(sacc[blk], a[blk], ONESH2, ONESH2);
            }
#pragma unroll
            for (int cp = 0; cp < 4; cp++) {
                uint32_t b0, b1, b2, b3;
                LDSM_X4(b0, b1, b2, b3, va + cp * (16 * VPITCH) + nt2 * 32);
                mma_k16h(o[0][2 * cp], a[0], b0, b1);
                mma_k16h(o[1][2 * cp], a[1], b0, b1);
                mma_k16h(o[0][2 * cp + 1], a[0], b2, b3);
                mma_k16h(o[1][2 * cp + 1], a[1], b2, b3);
            }
        }
    }

    __syncthreads();
    float* red = (float*)(dsm + OFF_V) + qg * (32 * REDP);
    float* reds = (float*)(dsm + OFF_V + 2 * 32 * REDP * 4);   // [2][32]

    if (kh == 1) {
#pragma unroll
        for (int blk = 0; blk < 2; blk++)
#pragma unroll
            for (int ct = 0; ct < 8; ct++) {
#pragma unroll
                for (int i = 0; i < 4; i++) {
                    int row = blk * 16 + g + (i >> 1) * 8;
                    red[row * REDP + ct * 8 + t4 * 2 + (i & 1)] = o[blk][ct][i];
                }
            }
        if (t4 == 0) {
#pragma unroll
            for (int blk = 0; blk < 2; blk++) {
                reds[qg * 32 + blk * 16 + g] = sacc[blk][0];
                reds[qg * 32 + blk * 16 + 8 + g] = sacc[blk][2];
            }
        }
    }
    __syncthreads();
    if (kh == 0) {
        float inv[2][2];
#pragma unroll
        for (int blk = 0; blk < 2; blk++) {
            inv[blk][0] = 1.0f / (sacc[blk][0] + reds[qg * 32 + blk * 16 + g]);
            inv[blk][1] = 1.0f / (sacc[blk][2] + reds[qg * 32 + blk * 16 + 8 + g]);
        }
        const float* gt = (const float*)(dsm + OFF_GATE);
        float* outb = out + (size_t)bb * C * N;
#pragma unroll
        for (int blk = 0; blk < 2; blk++)
#pragma unroll
            for (int ct = 0; ct < 8; ct++) {
#pragma unroll
                for (int i = 0; i < 4; i++) {
                    int row = blk * 16 + g + (i >> 1) * 8;
                    int ch = ct * 8 + t4 * 2 + (i & 1);
                    float v = o[blk][ct][i] + red[row * REDP + ch];
                    outb[(size_t)ch * N + q0 + row] = v * inv[blk][i >> 1] * gt[ch];
                }
            }
    }
}

// ---------------------------------------------------------------------------
extern "C" void kernel_launch(void* const* d_in, const int* in_sizes, int n_in,
                              void* d_out, int out_size) {
    const float* x  = (const float*)d_in[0];
    const float* Wq = (const float*)d_in[1];
    const float* bq = (const float*)d_in[2];
    const float* Wk = (const float*)d_in[3];
    const float* bk = (const float*)d_in[4];
    const float* Wv = (const float*)d_in[5];
    const float* bv = (const float*)d_in[6];
    const float* W1 = (const float*)d_in[7];
    const float* b1 = (const float*)d_in[8];
    const float* W2 = (const float*)d_in[9];
    const float* b2 = (const float*)d_in[10];
    float* out = (float*)d_out;

    cudaFuncSetAttribute(attn_kernel, cudaFuncAttributeMaxDynamicSharedMemorySize, SMEM_ATTN);

    qkv_kernel<<<B * 64, 256>>>(x, Wq, bq, Wk, bk, Wv, bv);
    gate_mlp_kernel<<<B, C>>>(W1, b1, W2, b2);
    attn_kernel<<<B * 64, 128, SMEM_ATTN>>>(out);
}

// round 16
// speedup vs baseline: 1.0718x; 1.0718x over previous
#include <cuda_runtime.h>
#include <cuda_bf16.h>
#include <cuda_fp16.h>
#include <cstdint>
#include <math.h>

#define B 4
#define C 64
#define N 4096

// ---------------------------------------------------------------------------
// Scratch (device globals, allocation-free rule)
// ---------------------------------------------------------------------------
__device__ __align__(16) __nv_bfloat16 g_Qb[B * N * 8];   // [b][n][8], scaled 0.125*log2e
__device__ __align__(16) __nv_bfloat16 g_Kb[B * N * 8];   // [b][m][8]
__device__ __align__(16) __half        g_Vt[B * C * N];   // [b][ch][m] transposed, fp16
__device__ float g_gate[B * C];
__device__ float g_part[B * 32 * C];                       // per-CTA channel sums

// ---------------------------------------------------------------------------
// Helpers
// ---------------------------------------------------------------------------
__device__ __forceinline__ uint32_t smem_u32(const void* p) {
    uint32_t a;
    asm("{ .reg .u64 t; cvta.to.shared.u64 t, %1; cvt.u32.u64 %0, t; }" : "=r"(a) : "l"(p));
    return a;
}
__device__ __forceinline__ uint32_t swz128(uint32_t o) {
    return o ^ ((o >> 3) & 0x70);
}
#define CVT2(r, a, b) \
    asm("cvt.rn.satfinite.bf16x2.f32 %0, %1, %2;" : "=r"(r) : "f"(b), "f"(a))
#define PACKH2(r, lo, hi) \
    asm("cvt.rn.f16x2.f32 %0, %1, %2;" : "=r"(r) : "f"(hi), "f"(lo))
#define EX2H2(r, s) \
    asm("ex2.approx.f16x2 %0, %1;" : "=r"(r) : "r"(s))

#define CP_ASYNC16(dst, src) \
    asm volatile("cp.async.cg.shared.global [%0], [%1], 16;" :: "r"(dst), "l"(src) : "memory")
#define CP_COMMIT() asm volatile("cp.async.commit_group;" ::: "memory")
#define CP_WAIT0()  asm volatile("cp.async.wait_group 0;" ::: "memory")

#define LDSM_X2(r0, r1, a) \
    asm volatile("ldmatrix.sync.aligned.m8n8.x2.shared.b16 {%0,%1}, [%2];" \
                 : "=r"(r0), "=r"(r1) : "r"(a))
#define LDSM_X4(r0, r1, r2, r3, a) \
    asm volatile("ldmatrix.sync.aligned.m8n8.x4.shared.b16 {%0,%1,%2,%3}, [%4];" \
                 : "=r"(r0), "=r"(r1), "=r"(r2), "=r"(r3) : "r"(a))

__device__ __forceinline__ void mma_k8(float& c0, float& c1, float& c2, float& c3,
                                       uint32_t a0, uint32_t a1, uint32_t b0) {
    asm volatile(
        "mma.sync.aligned.m16n8k8.row.col.f32.bf16.bf16.f32 "
        "{%0,%1,%2,%3}, {%4,%5}, {%6}, {%0,%1,%2,%3};"
        : "+f"(c0), "+f"(c1), "+f"(c2), "+f"(c3)
        : "r"(a0), "r"(a1), "r"(b0));
}
__device__ __forceinline__ void mma_k16(float* c, const uint32_t* a,
                                        uint32_t b0, uint32_t b1) {
    asm volatile(
        "mma.sync.aligned.m16n8k16.row.col.f32.bf16.bf16.f32 "
        "{%0,%1,%2,%3}, {%4,%5,%6,%7}, {%8,%9}, {%0,%1,%2,%3};"
        : "+f"(c[0]), "+f"(c[1]), "+f"(c[2]), "+f"(c[3])
        : "r"(a[0]), "r"(a[1]), "r"(a[2]), "r"(a[3]), "r"(b0), "r"(b1));
}
__device__ __forceinline__ void mma_k16h(float* c, const uint32_t* a,
                                         uint32_t b0, uint32_t b1) {
    asm volatile(
        "mma.sync.aligned.m16n8k16.row.col.f32.f16.f16.f32 "
        "{%0,%1,%2,%3}, {%4,%5,%6,%7}, {%8,%9}, {%0,%1,%2,%3};"
        : "+f"(c[0]), "+f"(c[1]), "+f"(c[2]), "+f"(c[3])
        : "r"(a[0]), "r"(a[1]), "r"(a[2]), "r"(a[3]), "r"(b0), "r"(b1));
}

#define QSCALE (0.125f * 1.4426950408889634f)

// ---------------------------------------------------------------------------
// Kernel 1: QKV via HMMA + fused SE partial sums (R12 proven: 128 px/CTA,
// dynamic smem, fp16 V). 128 CTAs x 256 thr.
// ---------------------------------------------------------------------------
#define XP 132
#define QOFF_W     0
#define QOFF_BIAS  10240
#define QOFF_XB    10880
#define QOFF_UNION 27264
#define QSMEM      (27264 + 64 * XP * 4)     // 61056

__global__ void __launch_bounds__(256) qkv_kernel(
    const float* __restrict__ x,
    const float* __restrict__ Wq, const float* __restrict__ bq,
    const float* __restrict__ Wk, const float* __restrict__ bk,
    const float* __restrict__ Wv, const float* __restrict__ bv) {
    extern __shared__ __align__(128) char sm[];
    uint32_t sb = smem_u32(sm);
    int t = threadIdx.x, lane = t & 31, w = t >> 5;
    int cta = blockIdx.x;
    int bb = cta >> 5;
    int n0 = (cta & 31) * 128;
    int pix0 = bb * N + n0;
    float* sXf = (float*)(sm + QOFF_UNION);
    float* sbias = (float*)(sm + QOFF_BIAS);

    for (int i = t; i < 1280; i += 256) {
        int r = i >> 4, c4 = i & 15;
        const float* src = (r < 8) ? (Wq + r * 64)
                         : (r < 16) ? (Wk + (r - 8) * 64)
                                    : (Wv + (r - 16) * 64);
        float4 ww = ((const float4*)src)[c4];
        uint32_t p0, p1;
        CVT2(p0, ww.x, ww.y);
        CVT2(p1, ww.z, ww.w);
        uint32_t gr = swz128((uint32_t)(r * 128 + (c4 >> 1) * 16)) + (c4 & 1) * 8;
        *(uint32_t*)(sm + QOFF_W + gr) = p0;
        *(uint32_t*)(sm + QOFF_W + gr + 4) = p1;
    }
    if (t < 80) sbias[t] = (t < 8) ? bq[t] : (t < 16) ? bk[t - 8] : bv[t - 16];

    {
        int q4 = lane, ch0 = w;
#pragma unroll
        for (int j = 0; j < 8; j++) {
            int ch = ch0 + 8 * j;
            float4 v = *(const float4*)(x + (size_t)(bb * C + ch) * N + n0 + q4 * 4);
            *(float4*)(sXf + ch * XP + q4 * 4) = v;
        }
    }
    __syncthreads();

    if (t < 64) {
        float s = 0.0f;
#pragma unroll 8
        for (int px = 0; px < 128; px++) s += sXf[t * XP + px];
        g_part[((size_t)bb * 32 + (cta & 31)) * C + t] = s;
    }

    {
        int px = t & 127, half = t >> 7;
#pragma unroll
        for (int s = 0; s < 4; s++) {
            int ch0 = half * 32 + s * 8;
            uint32_t u[4];
#pragma unroll
            for (int kk = 0; kk < 4; kk++) {
                float f0 = sXf[(ch0 + 2 * kk) * XP + px];
                float f1 = sXf[(ch0 + 2 * kk + 1) * XP + px];
                CVT2(u[kk], f0, f1);
            }
            uint32_t off = swz128((uint32_t)(px * 128 + half * 64 + s * 16));
            *(uint4*)(sm + QOFF_XB + off) = make_uint4(u[0], u[1], u[2], u[3]);
        }
    }
    __syncthreads();

    int wpx = w * 16;
    float o10[10][4] = {};
    {
        uint32_t a_row = (uint32_t)((wpx + (lane & 15)) * 128 + (lane >> 4) * 16);
        uint32_t b_row = (uint32_t)((((lane >> 4) * 8) + (lane & 7)) * 128 + ((lane >> 3) & 1) * 16);
#pragma unroll
        for (int ks = 0; ks < 4; ks++) {
            uint32_t a[4];
            LDSM_X4(a[0], a[1], a[2], a[3], sb + QOFF_XB + swz128(a_row + ks * 32));
#pragma unroll
            for (int ntp = 0; ntp < 5; ntp++) {
                uint32_t b0, b1, b2, b3;
                LDSM_X4(b0, b1, b2, b3,
                        sb + QOFF_W + swz128(b_row + (uint32_t)(ntp * 16 * 128) + ks * 32));
                mma_k16(o10[2 * ntp], a, b0, b1);
                mma_k16(o10[2 * ntp + 1], a, b2, b3);
            }
        }
    }

    int g = lane >> 2, t4 = lane & 3;
    {
        float bA = sbias[2 * t4], bB = sbias[2 * t4 + 1];
        uint32_t r0, r1;
        CVT2(r0, (o10[0][0] + bA) * QSCALE, (o10[0][1] + bB) * QSCALE);
        CVT2(r1, (o10[0][2] + bA) * QSCALE, (o10[0][3] + bB) * QSCALE);
        *(uint32_t*)(g_Qb + (size_t)(pix0 + wpx + g) * 8 + 2 * t4) = r0;
        *(uint32_t*)(g_Qb + (size_t)(pix0 + wpx + 8 + g) * 8 + 2 * t4) = r1;
    }
    {
        float bA = sbias[8 + 2 * t4], bB = sbias[8 + 2 * t4 + 1];
        uint32_t r0, r1;
        CVT2(r0, o10[1][0] + bA, o10[1][1] + bB);
        CVT2(r1, o10[1][2] + bA, o10[1][3] + bB);
        *(uint32_t*)(g_Kb + (size_t)(pix0 + wpx + g) * 8 + 2 * t4) = r0;
        *(uint32_t*)(g_Kb + (size_t)(pix0 + wpx + 8 + g) * 8 + 2 * t4) = r1;
    }
    __syncthreads();
    {
        __half* sV = (__half*)(sm + QOFF_UNION);   // [64][136]
#pragma unroll
        for (int nt = 2; nt < 10; nt++) {
            int ch = (nt - 2) * 8 + 2 * t4;
            float b0f = sbias[16 + ch], b1f = sbias[16 + ch + 1];
            sV[ch * 136 + wpx + g]           = __float2half(o10[nt][0] + b0f);
            sV[(ch + 1) * 136 + wpx + g]     = __float2half(o10[nt][1] + b1f);
            sV[ch * 136 + wpx + 8 + g]       = __float2half(o10[nt][2] + b0f);
            sV[(ch + 1) * 136 + wpx + 8 + g] = __float2half(o10[nt][3] + b1f);
        }
    }
    __syncthreads();
#pragma unroll
    for (int j = 0; j < 4; j++) {
        int i = t + 256 * j;
        int r = i >> 4, s = i & 15;
        uint4 v = *(const uint4*)(sm + QOFF_UNION + r * 272 + s * 16);
        *(uint4*)((char*)(g_Vt + (size_t)(bb * C + r) * N + n0 + s * 8)) = v;
    }
}

// ---------------------------------------------------------------------------
// Kernel 2: SE gate MLP. 4 blocks x 64 thr.
// ---------------------------------------------------------------------------
__global__ void gate_mlp_kernel(const float* __restrict__ W1, const float* __restrict__ b1,
                                const float* __restrict__ W2, const float* __restrict__ b2) {
    __shared__ float savg[C];
    __shared__ float shid[4];
    int b = blockIdx.x, t = threadIdx.x;
    float s = 0.0f;
#pragma unroll 8
    for (int j = 0; j < 32; j++) s += g_part[((size_t)b * 32 + j) * C + t];
    savg[t] = s * (1.0f / (float)N);
    __syncthreads();
    if (t < 4) {
        float h = b1[t];
#pragma unroll
        for (int c = 0; c < C; c++) h = fmaf(W1[t * C + c], savg[c], h);
        shid[t] = fmaxf(h, 0.0f);
    }
    __syncthreads();
    float gg = b2[t];
#pragma unroll
    for (int j = 0; j < 4; j++) gg = fmaf(W2[t * 4 + j], shid[j], gg);
    g_gate[b * C + t] = 1.0f / (1.0f + __expf(-gg));
}

// ---------------------------------------------------------------------------
// Kernel 3: HMMA flash attention (R12) with row sums moved OFF the tensor
// pipe: HADD2 + f32 accumulate replaces the 2 ones-column MMAs per chunk.
// ---------------------------------------------------------------------------
#define OFF_GATE 0
#define OFF_K    256
#define OFF_V    (256 + 8192)
#define SMEM_ATTN (256 + 8192 + 4 * 17408)
#define VPITCH 272
#define REDP 66

__global__ void __launch_bounds__(128, 2) attn_kernel(float* __restrict__ out) {
    extern __shared__ char dsm[];
    uint32_t sb = smem_u32(dsm);
    int tid = threadIdx.x, w = tid >> 5, lane = tid & 31;
    int g = lane >> 2, t4 = lane & 3;
    int qg = w & 1, kh = w >> 1;
    int bb = blockIdx.x >> 6, qb = blockIdx.x & 63;
    int q0 = qb * 64 + qg * 32;

    if (tid < C) ((float*)(dsm + OFF_GATE))[tid] = g_gate[bb * C + tid];

    uint32_t qa[4];
    {
        const __nv_bfloat16* Qp = g_Qb + ((size_t)bb * N + q0) * 8 + t4 * 2;
#pragma unroll
        for (int r = 0; r < 4; r++)
            qa[r] = *(const uint32_t*)(Qp + (size_t)(r * 8 + g) * 8);
    }

    const char* kgb = (const char*)(g_Kb + (size_t)bb * N * 8);
    const char* vgb = (const char*)(g_Vt + (size_t)bb * C * N);

    uint32_t kfb = sb + OFF_K + kh * 4096 + (lane & 15) * 16;
    int vg2 = lane >> 3, vr = lane & 7;
    uint32_t vfb = sb + OFF_V + kh * 34816
                 + (uint32_t)(((vg2 >> 1) * 8 + vr) * VPITCH + (vg2 & 1) * 16);

#pragma unroll
    for (int h = 0; h < 2; h++) {
        int key0 = h * 2048;
        CP_ASYNC16(sb + OFF_K + h * 4096 + tid * 16, kgb + (size_t)key0 * 16 + tid * 16);
#pragma unroll
        for (int j = 0; j < 8; j++) {
            int id = tid + 128 * j, row = id >> 4, c16 = id & 15;
            CP_ASYNC16(sb + OFF_V + h * 34816 + row * VPITCH + c16 * 16,
                       vgb + ((size_t)row * N + key0) * 2 + c16 * 16);
        }
    }
    CP_COMMIT();

    float o[2][8][4] = {};
    float sums[4] = {0.f, 0.f, 0.f, 0.f};   // [2blk+rowhalf]; lane-partial (keys 4t4..)

#pragma unroll 1
    for (int kt = 0; kt < 16; kt++) {
        int buf = kt & 1;
        CP_WAIT0();
        __syncthreads();
        if (kt + 1 < 16) {
            int nb = (kt + 1) & 1;
#pragma unroll
            for (int h = 0; h < 2; h++) {
                int key0 = h * 2048 + (kt + 1) * 128;
                CP_ASYNC16(sb + OFF_K + (h * 2 + nb) * 2048 + tid * 16,
                           kgb + (size_t)key0 * 16 + tid * 16);
#pragma unroll
                for (int j = 0; j < 8; j++) {
                    int id = tid + 128 * j, row = id >> 4, c16 = id & 15;
                    CP_ASYNC16(sb + OFF_V + (h * 2 + nb) * 17408 + row * VPITCH + c16 * 16,
                               vgb + ((size_t)row * N + key0) * 2 + c16 * 16);
                }
            }
            CP_COMMIT();
        }
        uint32_t ka = kfb + buf * 2048;
        uint32_t va = vfb + buf * 17408;
#pragma unroll
        for (int nt2 = 0; nt2 < 8; nt2++) {
            uint32_t kk0, kk1;
            LDSM_X2(kk0, kk1, ka + nt2 * 256);
            uint32_t a[2][4];
#pragma unroll
            for (int blk = 0; blk < 2; blk++) {
                float c0 = 0, c1 = 0, c2 = 0, c3 = 0, c4 = 0, c5 = 0, c6 = 0, c7 = 0;
                mma_k8(c0, c1, c2, c3, qa[2 * blk], qa[2 * blk + 1], kk0);
                mma_k8(c4, c5, c6, c7, qa[2 * blk], qa[2 * blk + 1], kk1);
                uint32_t s01, s23, s45, s67;
                PACKH2(s01, c0, c1);
                PACKH2(s23, c2, c3);
                PACKH2(s45, c4, c5);
                PACKH2(s67, c6, c7);
                EX2H2(a[blk][0], s01);
                EX2H2(a[blk][1], s23);
                EX2H2(a[blk][2], s45);
                EX2H2(a[blk][3], s67);
                // row sums on FMA/ALU pipes (tensor pipe is the bottleneck)
                __half2 h0 = __hadd2(*(__half2*)&a[blk][0], *(__half2*)&a[blk][2]); // row g
                __half2 h1 = __hadd2(*(__half2*)&a[blk][1], *(__half2*)&a[blk][3]); // row g+8
                float2 f0 = __half22float2(h0);
                float2 f1 = __half22float2(h1);
                sums[2 * blk]     += f0.x + f0.y;
                sums[2 * blk + 1] += f1.x + f1.y;
            }
#pragma unroll
            for (int cp = 0; cp < 4; cp++) {
                uint32_t b0, b1, b2, b3;
                LDSM_X4(b0, b1, b2, b3, va + cp * (16 * VPITCH) + nt2 * 32);
                mma_k16h(o[0][2 * cp], a[0], b0, b1);
                mma_k16h(o[1][2 * cp], a[1], b0, b1);
                mma_k16h(o[0][2 * cp + 1], a[0], b2, b3);
                mma_k16h(o[1][2 * cp + 1], a[1], b2, b3);
            }
        }
    }

    // reduce lane-partial sums across the 4 lanes of each row group
#pragma unroll
    for (int j = 0; j < 4; j++) {
        sums[j] += __shfl_xor_sync(0xFFFFFFFFu, sums[j], 1);
        sums[j] += __shfl_xor_sync(0xFFFFFFFFu, sums[j], 2);
    }

    __syncthreads();
    float* red = (float*)(dsm + OFF_V) + qg * (32 * REDP);
    float* reds = (float*)(dsm + OFF_V + 2 * 32 * REDP * 4);   // [2][32]

    if (kh == 1) {
#pragma unroll
        for (int blk = 0; blk < 2; blk++)
#pragma unroll
            for (int ct = 0; ct < 8; ct++) {
#pragma unroll
                for (int i = 0; i < 4; i++) {
                    int row = blk * 16 + g + (i >> 1) * 8;
                    red[row * REDP + ct * 8 + t4 * 2 + (i & 1)] = o[blk][ct][i];
                }
            }
        if (t4 == 0) {
#pragma unroll
            for (int blk = 0; blk < 2; blk++) {
                reds[qg * 32 + blk * 16 + g] = sums[2 * blk];
                reds[qg * 32 + blk * 16 + 8 + g] = sums[2 * blk + 1];
            }
        }
    }
    __syncthreads();
    if (kh == 0) {
        float inv[2][2];
#pragma unroll
        for (int blk = 0; blk < 2; blk++) {
            inv[blk][0] = 1.0f / (sums[2 * blk] + reds[qg * 32 + blk * 16 + g]);
            inv[blk][1] = 1.0f / (sums[2 * blk + 1] + reds[qg * 32 + blk * 16 + 8 + g]);
        }
        const float* gt = (const float*)(dsm + OFF_GATE);
        float* outb = out + (size_t)bb * C * N;
#pragma unroll
        for (int blk = 0; blk < 2; blk++)
#pragma unroll
            for (int ct = 0; ct < 8; ct++) {
#pragma unroll
                for (int i = 0; i < 4; i++) {
                    int row = blk * 16 + g + (i >> 1) * 8;
                    int ch = ct * 8 + t4 * 2 + (i & 1);
                    float v = o[blk][ct][i] + red[row * REDP + ch];
                    outb[(size_t)ch * N + q0 + row] = v * inv[blk][i >> 1] * gt[ch];
                }
            }
    }
}

// ---------------------------------------------------------------------------
extern "C" void kernel_launch(void* const* d_in, const int* in_sizes, int n_in,
                              void* d_out, int out_size) {
    const float* x  = (const float*)d_in[0];
    const float* Wq = (const float*)d_in[1];
    const float* bq = (const float*)d_in[2];
    const float* Wk = (const float*)d_in[3];
    const float* bk = (const float*)d_in[4];
    const float* Wv = (const float*)d_in[5];
    const float* bv = (const float*)d_in[6];
    const float* W1 = (const float*)d_in[7];
    const float* b1 = (const float*)d_in[8];
    const float* W2 = (const float*)d_in[9];
    const float* b2 = (const float*)d_in[10];
    float* out = (float*)d_out;

    cudaFuncSetAttribute(qkv_kernel, cudaFuncAttributeMaxDynamicSharedMemorySize, QSMEM);
    cudaFuncSetAttribute(attn_kernel, cudaFuncAttributeMaxDynamicSharedMemorySize, SMEM_ATTN);

    qkv_kernel<<<B * 32, 256, QSMEM>>>(x, Wq, bq, Wk, bk, Wv, bv);
    gate_mlp_kernel<<<B, C>>>(W1, b1, W2, b2);
    attn_kernel<<<B * 64, 128, SMEM_ATTN>>>(out);
}

// round 17
// speedup vs baseline: 1.1395x; 1.0632x over previous
#include <cuda_runtime.h>
#include <cuda_bf16.h>
#include <cuda_fp16.h>
#include <cstdint>
#include <math.h>

#define B 4
#define C 64
#define N 4096

// ---------------------------------------------------------------------------
// Scratch (device globals, allocation-free rule)
// ---------------------------------------------------------------------------
__device__ __align__(16) __nv_bfloat16 g_Qb[B * N * 8];   // [b][n][8], scaled 0.125*log2e
__device__ __align__(16) __nv_bfloat16 g_Kb[B * N * 8];   // [b][m][8]
__device__ __align__(16) __half        g_Vt[B * C * N];   // [b][ch][m] transposed, fp16
__device__ float g_gate[B * C];
__device__ float g_part[B * 32 * C];                       // per-CTA channel sums

// ---------------------------------------------------------------------------
// Helpers
// ---------------------------------------------------------------------------
__device__ __forceinline__ uint32_t smem_u32(const void* p) {
    uint32_t a;
    asm("{ .reg .u64 t; cvta.to.shared.u64 t, %1; cvt.u32.u64 %0, t; }" : "=r"(a) : "l"(p));
    return a;
}
__device__ __forceinline__ uint32_t swz128(uint32_t o) {
    return o ^ ((o >> 3) & 0x70);
}
#define CVT2(r, a, b) \
    asm("cvt.rn.satfinite.bf16x2.f32 %0, %1, %2;" : "=r"(r) : "f"(b), "f"(a))
#define PACKH2(r, lo, hi) \
    asm("cvt.rn.f16x2.f32 %0, %1, %2;" : "=r"(r) : "f"(hi), "f"(lo))
#define EX2H2(r, s) \
    asm("ex2.approx.f16x2 %0, %1;" : "=r"(r) : "r"(s))
#define ONESH2 0x3C003C00u

#define CP_ASYNC16(dst, src) \
    asm volatile("cp.async.cg.shared.global [%0], [%1], 16;" :: "r"(dst), "l"(src) : "memory")
#define CP_COMMIT() asm volatile("cp.async.commit_group;" ::: "memory")
#define CP_WAIT0()  asm volatile("cp.async.wait_group 0;" ::: "memory")

#define LDSM_X2(r0, r1, a) \
    asm volatile("ldmatrix.sync.aligned.m8n8.x2.shared.b16 {%0,%1}, [%2];" \
                 : "=r"(r0), "=r"(r1) : "r"(a))
#define LDSM_X4(r0, r1, r2, r3, a) \
    asm volatile("ldmatrix.sync.aligned.m8n8.x4.shared.b16 {%0,%1,%2,%3}, [%4];" \
                 : "=r"(r0), "=r"(r1), "=r"(r2), "=r"(r3) : "r"(a))

__device__ __forceinline__ void mma_k8(float& c0, float& c1, float& c2, float& c3,
                                       uint32_t a0, uint32_t a1, uint32_t b0) {
    asm volatile(
        "mma.sync.aligned.m16n8k8.row.col.f32.bf16.bf16.f32 "
        "{%0,%1,%2,%3}, {%4,%5}, {%6}, {%0,%1,%2,%3};"
        : "+f"(c0), "+f"(c1), "+f"(c2), "+f"(c3)
        : "r"(a0), "r"(a1), "r"(b0));
}
__device__ __forceinline__ void mma_k16(float* c, const uint32_t* a,
                                        uint32_t b0, uint32_t b1) {
    asm volatile(
        "mma.sync.aligned.m16n8k16.row.col.f32.bf16.bf16.f32 "
        "{%0,%1,%2,%3}, {%4,%5,%6,%7}, {%8,%9}, {%0,%1,%2,%3};"
        : "+f"(c[0]), "+f"(c[1]), "+f"(c[2]), "+f"(c[3])
        : "r"(a[0]), "r"(a[1]), "r"(a[2]), "r"(a[3]), "r"(b0), "r"(b1));
}
__device__ __forceinline__ void mma_k16h(float* c, const uint32_t* a,
                                         uint32_t b0, uint32_t b1) {
    asm volatile(
        "mma.sync.aligned.m16n8k16.row.col.f32.f16.f16.f32 "
        "{%0,%1,%2,%3}, {%4,%5,%6,%7}, {%8,%9}, {%0,%1,%2,%3};"
        : "+f"(c[0]), "+f"(c[1]), "+f"(c[2]), "+f"(c[3])
        : "r"(a[0]), "r"(a[1]), "r"(a[2]), "r"(a[3]), "r"(b0), "r"(b1));
}

#define QSCALE (0.125f * 1.4426950408889634f)

// ---------------------------------------------------------------------------
// Kernel 1: QKV via HMMA + fused SE partial sums.
// 128 CTAs x 256 thr, 128 px/CTA. Direct gmem->reg->bf16-swizzled-smem path
// (no fp32 smem bounce). Static smem 46720 B:
//   QOFF_W    bf16 [80][64] swizzled        (10240)
//   QOFF_BIAS 80 f32 (+pad)                  (640)
//   QOFF_XB   bf16 [128px][64ch] swizzled    (16384)
//   QOFF_SP   SE partials f32 [64ch][8pg]    (2048)
//   QOFF_VB   V-stage f16 [64][136]          (17408)
// ---------------------------------------------------------------------------
#define QOFF_W     0
#define QOFF_BIAS  10240
#define QOFF_XB    10880
#define QOFF_SP    27264
#define QOFF_VB    29312
#define QSMEM      46720

__global__ void __launch_bounds__(256) qkv_kernel(
    const float* __restrict__ x,
    const float* __restrict__ Wq, const float* __restrict__ bq,
    const float* __restrict__ Wk, const float* __restrict__ bk,
    const float* __restrict__ Wv, const float* __restrict__ bv) {
    __shared__ __align__(128) char sm[QSMEM];
    uint32_t sb = smem_u32(sm);
    int t = threadIdx.x, lane = t & 31, w = t >> 5;
    int cta = blockIdx.x;
    int bb = cta >> 5;
    int n0 = (cta & 31) * 128;
    int pix0 = bb * N + n0;
    float* sbias = (float*)(sm + QOFF_BIAS);
    float* sp = (float*)(sm + QOFF_SP);

    // weights -> bf16 swizzled; biases
    for (int i = t; i < 1280; i += 256) {            // 80 rows x 16 float4
        int r = i >> 4, c4 = i & 15;
        const float* src = (r < 8) ? (Wq + r * 64)
                         : (r < 16) ? (Wk + (r - 8) * 64)
                                    : (Wv + (r - 16) * 64);
        float4 ww = ((const float4*)src)[c4];
        uint32_t p0, p1;
        CVT2(p0, ww.x, ww.y);
        CVT2(p1, ww.z, ww.w);
        uint32_t gr = swz128((uint32_t)(r * 128 + (c4 >> 1) * 16)) + (c4 & 1) * 8;
        *(uint32_t*)(sm + QOFF_W + gr) = p0;
        *(uint32_t*)(sm + QOFF_W + gr + 4) = p1;
    }
    if (t < 80) sbias[t] = (t < 8) ? bq[t] : (t < 16) ? bk[t - 8] : bv[t - 16];

    // x: direct load -> cvt -> swizzled bf16 STS. thread = (chpair cp, pxgroup pg)
    {
        int cp = t & 31, pg = t >> 5;
        const float4* xa = (const float4*)(x + (size_t)(bb * C + 2 * cp) * N + n0 + pg * 16);
        const float4* xb = (const float4*)(x + (size_t)(bb * C + 2 * cp + 1) * N + n0 + pg * 16);
        float4 A[4], Bv[4];
#pragma unroll
        for (int j = 0; j < 4; j++) { A[j] = xa[j]; Bv[j] = xb[j]; }
        const float* Af = (const float*)A;
        const float* Bf = (const float*)Bv;
        int grp = cp >> 2, inr = cp & 3;
        float sa = 0.0f, sbv = 0.0f;
#pragma unroll
        for (int j = 0; j < 16; j++) {
            int px = pg * 16 + j;
            uint32_t u;
            CVT2(u, Af[j], Bf[j]);
            *(uint32_t*)(sm + QOFF_XB + swz128((uint32_t)(px * 128 + grp * 16)) + inr * 4) = u;
            sa += Af[j];
            sbv += Bf[j];
        }
        sp[(2 * cp) * 8 + pg] = sa;
        sp[(2 * cp + 1) * 8 + pg] = sbv;
    }
    __syncthreads();

    // SE partial sums -> g_part
    if (t < 64) {
        float s = 0.0f;
#pragma unroll
        for (int pg = 0; pg < 8; pg++) s += sp[t * 8 + pg];
        g_part[((size_t)bb * 32 + (cta & 31)) * C + t] = s;
    }

    // MMA: warp w handles px rows [w*16, w*16+16), all 80 outputs (R12 layout)
    int wpx = w * 16;
    float o10[10][4] = {};
    {
        uint32_t a_row = (uint32_t)((wpx + (lane & 15)) * 128 + (lane >> 4) * 16);
        uint32_t b_row = (uint32_t)((((lane >> 4) * 8) + (lane & 7)) * 128 + ((lane >> 3) & 1) * 16);
#pragma unroll
        for (int ks = 0; ks < 4; ks++) {
            uint32_t a[4];
            LDSM_X4(a[0], a[1], a[2], a[3], sb + QOFF_XB + swz128(a_row + ks * 32));
#pragma unroll
            for (int ntp = 0; ntp < 5; ntp++) {
                uint32_t b0, b1, b2, b3;
                LDSM_X4(b0, b1, b2, b3,
                        sb + QOFF_W + swz128(b_row + (uint32_t)(ntp * 16 * 128) + ks * 32));
                mma_k16(o10[2 * ntp], a, b0, b1);
                mma_k16(o10[2 * ntp + 1], a, b2, b3);
            }
        }
    }

    int g = lane >> 2, t4 = lane & 3;
    // Q (ntile 0)
    {
        float bA = sbias[2 * t4], bB = sbias[2 * t4 + 1];
        uint32_t r0, r1;
        CVT2(r0, (o10[0][0] + bA) * QSCALE, (o10[0][1] + bB) * QSCALE);
        CVT2(r1, (o10[0][2] + bA) * QSCALE, (o10[0][3] + bB) * QSCALE);
        *(uint32_t*)(g_Qb + (size_t)(pix0 + wpx + g) * 8 + 2 * t4) = r0;
        *(uint32_t*)(g_Qb + (size_t)(pix0 + wpx + 8 + g) * 8 + 2 * t4) = r1;
    }
    // K (ntile 1)
    {
        float bA = sbias[8 + 2 * t4], bB = sbias[8 + 2 * t4 + 1];
        uint32_t r0, r1;
        CVT2(r0, o10[1][0] + bA, o10[1][1] + bB);
        CVT2(r1, o10[1][2] + bA, o10[1][3] + bB);
        *(uint32_t*)(g_Kb + (size_t)(pix0 + wpx + g) * 8 + 2 * t4) = r0;
        *(uint32_t*)(g_Kb + (size_t)(pix0 + wpx + 8 + g) * 8 + 2 * t4) = r1;
    }
    // V (ntiles 2-9) -> dedicated f16 bounce region (no pre-sync needed)
    {
        __half* sV = (__half*)(sm + QOFF_VB);   // [64][136]
#pragma unroll
        for (int nt = 2; nt < 10; nt++) {
            int ch = (nt - 2) * 8 + 2 * t4;
            float b0f = sbias[16 + ch], b1f = sbias[16 + ch + 1];
            sV[ch * 136 + wpx + g]           = __float2half(o10[nt][0] + b0f);
            sV[(ch + 1) * 136 + wpx + g]     = __float2half(o10[nt][1] + b1f);
            sV[ch * 136 + wpx + 8 + g]       = __float2half(o10[nt][2] + b0f);
            sV[(ch + 1) * 136 + wpx + 8 + g] = __float2half(o10[nt][3] + b1f);
        }
    }
    __syncthreads();
    // coalesced copy V-stage -> g_Vt
#pragma unroll
    for (int j = 0; j < 4; j++) {
        int i = t + 256 * j;
        int r = i >> 4, s = i & 15;
        uint4 v = *(const uint4*)(sm + QOFF_VB + r * 272 + s * 16);
        *(uint4*)((char*)(g_Vt + (size_t)(bb * C + r) * N + n0 + s * 8)) = v;
    }
}

// ---------------------------------------------------------------------------
// Kernel 2: SE gate MLP. 4 blocks x 64 thr.
// ---------------------------------------------------------------------------
__global__ void gate_mlp_kernel(const float* __restrict__ W1, const float* __restrict__ b1,
                                const float* __restrict__ W2, const float* __restrict__ b2) {
    __shared__ float savg[C];
    __shared__ float shid[4];
    int b = blockIdx.x, t = threadIdx.x;
    float s = 0.0f;
#pragma unroll 8
    for (int j = 0; j < 32; j++) s += g_part[((size_t)b * 32 + j) * C + t];
    savg[t] = s * (1.0f / (float)N);
    __syncthreads();
    if (t < 4) {
        float h = b1[t];
#pragma unroll
        for (int c = 0; c < C; c++) h = fmaf(W1[t * C + c], savg[c], h);
        shid[t] = fmaxf(h, 0.0f);
    }
    __syncthreads();
    float gg = b2[t];
#pragma unroll
    for (int j = 0; j < 4; j++) gg = fmaf(W2[t * 4 + j], shid[j], gg);
    g_gate[b * C + t] = 1.0f / (1.0f + __expf(-gg));
}

// ---------------------------------------------------------------------------
// Kernel 3: HMMA flash attention (R12 verbatim — best measured: ~38 us).
// ---------------------------------------------------------------------------
#define OFF_GATE 0
#define OFF_K    256
#define OFF_V    (256 + 8192)
#define SMEM_ATTN (256 + 8192 + 4 * 17408)
#define VPITCH 272
#define REDP 66

__global__ void __launch_bounds__(128, 2) attn_kernel(float* __restrict__ out) {
    extern __shared__ char dsm[];
    uint32_t sb = smem_u32(dsm);
    int tid = threadIdx.x, w = tid >> 5, lane = tid & 31;
    int g = lane >> 2, t4 = lane & 3;
    int qg = w & 1, kh = w >> 1;
    int bb = blockIdx.x >> 6, qb = blockIdx.x & 63;
    int q0 = qb * 64 + qg * 32;

    if (tid < C) ((float*)(dsm + OFF_GATE))[tid] = g_gate[bb * C + tid];

    uint32_t qa[4];
    {
        const __nv_bfloat16* Qp = g_Qb + ((size_t)bb * N + q0) * 8 + t4 * 2;
#pragma unroll
        for (int r = 0; r < 4; r++)
            qa[r] = *(const uint32_t*)(Qp + (size_t)(r * 8 + g) * 8);
    }

    const char* kgb = (const char*)(g_Kb + (size_t)bb * N * 8);
    const char* vgb = (const char*)(g_Vt + (size_t)bb * C * N);

    uint32_t kfb = sb + OFF_K + kh * 4096 + (lane & 15) * 16;
    int vg2 = lane >> 3, vr = lane & 7;
    uint32_t vfb = sb + OFF_V + kh * 34816
                 + (uint32_t)(((vg2 >> 1) * 8 + vr) * VPITCH + (vg2 & 1) * 16);

#pragma unroll
    for (int h = 0; h < 2; h++) {
        int key0 = h * 2048;
        CP_ASYNC16(sb + OFF_K + h * 4096 + tid * 16, kgb + (size_t)key0 * 16 + tid * 16);
#pragma unroll
        for (int j = 0; j < 8; j++) {
            int id = tid + 128 * j, row = id >> 4, c16 = id & 15;
            CP_ASYNC16(sb + OFF_V + h * 34816 + row * VPITCH + c16 * 16,
                       vgb + ((size_t)row * N + key0) * 2 + c16 * 16);
        }
    }
    CP_COMMIT();

    float o[2][8][4] = {};
    float sacc[2][4] = {};     // ones-column row sums

#pragma unroll 1
    for (int kt = 0; kt < 16; kt++) {
        int buf = kt & 1;
        CP_WAIT0();
        __syncthreads();
        if (kt + 1 < 16) {
            int nb = (kt + 1) & 1;
#pragma unroll
            for (int h = 0; h < 2; h++) {
                int key0 = h * 2048 + (kt + 1) * 128;
                CP_ASYNC16(sb + OFF_K + (h * 2 + nb) * 2048 + tid * 16,
                           kgb + (size_t)key0 * 16 + tid * 16);
#pragma unroll
                for (int j = 0; j < 8; j++) {
                    int id = tid + 128 * j, row = id >> 4, c16 = id & 15;
                    CP_ASYNC16(sb + OFF_V + (h * 2 + nb) * 17408 + row * VPITCH + c16 * 16,
                               vgb + ((size_t)row * N + key0) * 2 + c16 * 16);
                }
            }
            CP_COMMIT();
        }
        uint32_t ka = kfb + buf * 2048;
        uint32_t va = vfb + buf * 17408;
#pragma unroll
        for (int nt2 = 0; nt2 < 8; nt2++) {
            uint32_t kk0, kk1;
            LDSM_X2(kk0, kk1, ka + nt2 * 256);
            uint32_t a[2][4];
#pragma unroll
            for (int blk = 0; blk < 2; blk++) {
                float c0 = 0, c1 = 0, c2 = 0, c3 = 0, c4 = 0, c5 = 0, c6 = 0, c7 = 0;
                mma_k8(c0, c1, c2, c3, qa[2 * blk], qa[2 * blk + 1], kk0);
                mma_k8(c4, c5, c6, c7, qa[2 * blk], qa[2 * blk + 1], kk1);
                uint32_t s01, s23, s45, s67;
                PACKH2(s01, c0, c1);
                PACKH2(s23, c2, c3);
                PACKH2(s45, c4, c5);
                PACKH2(s67, c6, c7);
                EX2H2(a[blk][0], s01);
                EX2H2(a[blk][1], s23);
                EX2H2(a[blk][2], s45);
                EX2H2(a[blk][3], s67);
                mma_k16h(sacc[blk], a[blk], ONESH2, ONESH2);
            }
#pragma unroll
            for (int cp = 0; cp < 4; cp++) {
                uint32_t b0, b1, b2, b3;
                LDSM_X4(b0, b1, b2, b3, va + cp * (16 * VPITCH) + nt2 * 32);
                mma_k16h(o[0][2 * cp], a[0], b0, b1);
                mma_k16h(o[1][2 * cp], a[1], b0, b1);
                mma_k16h(o[0][2 * cp + 1], a[0], b2, b3);
                mma_k16h(o[1][2 * cp + 1], a[1], b2, b3);
            }
        }
    }

    __syncthreads();
    float* red = (float*)(dsm + OFF_V) + qg * (32 * REDP);
    float* reds = (float*)(dsm + OFF_V + 2 * 32 * REDP * 4);   // [2][32]

    if (kh == 1) {
#pragma unroll
        for (int blk = 0; blk < 2; blk++)
#pragma unroll
            for (int ct = 0; ct < 8; ct++) {
#pragma unroll
                for (int i = 0; i < 4; i++) {
                    int row = blk * 16 + g + (i >> 1) * 8;
                    red[row * REDP + ct * 8 + t4 * 2 + (i & 1)] = o[blk][ct][i];
                }
            }
        if (t4 == 0) {
#pragma unroll
            for (int blk = 0; blk < 2; blk++) {
                reds[qg * 32 + blk * 16 + g] = sacc[blk][0];
                reds[qg * 32 + blk * 16 + 8 + g] = sacc[blk][2];
            }
        }
    }
    __syncthreads();
    if (kh == 0) {
        float inv[2][2];
#pragma unroll
        for (int blk = 0; blk < 2; blk++) {
            inv[blk][0] = 1.0f / (sacc[blk][0] + reds[qg * 32 + blk * 16 + g]);
            inv[blk][1] = 1.0f / (sacc[blk][2] + reds[qg * 32 + blk * 16 + 8 + g]);
        }
        const float* gt = (const float*)(dsm + OFF_GATE);
        float* outb = out + (size_t)bb * C * N;
#pragma unroll
        for (int blk = 0; blk < 2; blk++)
#pragma unroll
            for (int ct = 0; ct < 8; ct++) {
#pragma unroll
                for (int i = 0; i < 4; i++) {
                    int row = blk * 16 + g + (i >> 1) * 8;
                    int ch = ct * 8 + t4 * 2 + (i & 1);
                    float v = o[blk][ct][i] + red[row * REDP + ch];
                    outb[(size_t)ch * N + q0 + row] = v * inv[blk][i >> 1] * gt[ch];
                }
            }
    }
}

// ---------------------------------------------------------------------------
extern "C" void kernel_launch(void* const* d_in, const int* in_sizes, int n_in,
                              void* d_out, int out_size) {
    const float* x  = (const float*)d_in[0];
    const float* Wq = (const float*)d_in[1];
    const float* bq = (const float*)d_in[2];
    const float* Wk = (const float*)d_in[3];
    const float* bk = (const float*)d_in[4];
    const float* Wv = (const float*)d_in[5];
    const float* bv = (const float*)d_in[6];
    const float* W1 = (const float*)d_in[7];
    const float* b1 = (const float*)d_in[8];
    const float* W2 = (const float*)d_in[9];
    const float* b2 = (const float*)d_in[10];
    float* out = (float*)d_out;

    cudaFuncSetAttribute(attn_kernel, cudaFuncAttributeMaxDynamicSharedMemorySize, SMEM_ATTN);

    qkv_kernel<<<B * 32, 256>>>(x, Wq, bq, Wk, bk, Wv, bv);
    gate_mlp_kernel<<<B, C>>>(W1, b1, W2, b2);
    attn_kernel<<<B * 64, 128, SMEM_ATTN>>>(out);
}